// round 15
// baseline (speedup 1.0000x reference)
#include <cuda_runtime.h>
#include <cuda_fp16.h>
#include <cstdint>

// Problem constants
#define BB   128
#define HH   12
#define DH   64
#define DIM  768
#define NN   197
#define MTOT (BB * NN)          // 25216 = 197 * 128
#define TABLE 730
#define NP   208                // padded cols for bias / S
#define NPR  256                // padded rows for bias

// ---------------- scratch (device globals; no allocations allowed) ----------
__device__ alignas(16) __half g_Xh[(size_t)MTOT * DIM];
__device__ alignas(16) __half g_Wqkv[(size_t)3 * DIM * DIM];
__device__ alignas(16) __half g_Wp[(size_t)DIM * DIM];
__device__ alignas(16) __half g_Q[(size_t)BB * HH * NN * DH];
__device__ alignas(16) __half g_K[(size_t)BB * HH * NN * DH];
__device__ alignas(16) __half g_V[(size_t)BB * HH * NN * DH];
__device__ alignas(16) __half g_AO[(size_t)MTOT * DIM];
__device__ alignas(16) __half g_bias[(size_t)HH * NPR * NP];   // fp16 bias

// ---------------- helpers ----------------
__device__ __forceinline__ unsigned smem_u32(const void* p) {
    return (unsigned)__cvta_generic_to_shared(p);
}
__device__ __forceinline__ unsigned h2_as_u(__half2 h) {
    return *reinterpret_cast<unsigned*>(&h);
}
__device__ __forceinline__ void cpa16s(unsigned sdst, const void* src) {
    asm volatile("cp.async.cg.shared.global [%0], [%1], 16;" :: "r"(sdst), "l"(src));
}
#define CP_COMMIT() asm volatile("cp.async.commit_group;")
#define CP_WAIT(n)  asm volatile("cp.async.wait_group %0;" :: "n"(n))

__device__ __forceinline__ void ldsm4(unsigned& r0, unsigned& r1, unsigned& r2,
                                      unsigned& r3, unsigned a) {
    asm volatile("ldmatrix.sync.aligned.m8n8.x4.shared.b16 {%0,%1,%2,%3}, [%4];"
                 : "=r"(r0), "=r"(r1), "=r"(r2), "=r"(r3) : "r"(a));
}
__device__ __forceinline__ void ldsm4p(unsigned& r0, unsigned& r1, unsigned& r2,
                                       unsigned& r3, const void* p) {
    ldsm4(r0, r1, r2, r3, smem_u32(p));
}
__device__ __forceinline__ void ldsm4t(unsigned& r0, unsigned& r1, unsigned& r2,
                                       unsigned& r3, const void* p) {
    unsigned a = smem_u32(p);
    asm volatile("ldmatrix.sync.aligned.m8n8.x4.trans.shared.b16 {%0,%1,%2,%3}, [%4];"
                 : "=r"(r0), "=r"(r1), "=r"(r2), "=r"(r3) : "r"(a));
}
__device__ __forceinline__ void mma16816(float* c, const unsigned* a,
                                         unsigned b0, unsigned b1) {
    asm volatile(
        "mma.sync.aligned.m16n8k16.row.col.f32.f16.f16.f32 "
        "{%0,%1,%2,%3}, {%4,%5,%6,%7}, {%8,%9}, {%0,%1,%2,%3};"
        : "+f"(c[0]), "+f"(c[1]), "+f"(c[2]), "+f"(c[3])
        : "r"(a[0]), "r"(a[1]), "r"(a[2]), "r"(a[3]), "r"(b0), "r"(b1));
}

// ---------------- converts + bias ----------------
#define NX2  (MTOT * DIM / 2)
#define NW12 (3 * DIM * DIM / 2)
#define NW22 (DIM * DIM / 2)
#define TOTB (HH * NPR * NP)
__global__ void f2h_x(const float* __restrict__ x) {
    int i = blockIdx.x * blockDim.x + threadIdx.x;
    if (i < NX2) {
        float2 v = reinterpret_cast<const float2*>(x)[i];
        reinterpret_cast<__half2*>(g_Xh)[i] = __floats2half2_rn(v.x, v.y);
    }
}
// weights convert + fp16 bias expansion fused
__global__ void f2h_wb(const float* __restrict__ qkvw, const float* __restrict__ projw,
                       const float* __restrict__ tab, const int* __restrict__ ridx) {
    int i = blockIdx.x * blockDim.x + threadIdx.x;
    if (i < NW12) {
        float2 v = reinterpret_cast<const float2*>(qkvw)[i];
        reinterpret_cast<__half2*>(g_Wqkv)[i] = __floats2half2_rn(v.x, v.y);
    } else if (i < NW12 + NW22) {
        int j = i - NW12;
        float2 v = reinterpret_cast<const float2*>(projw)[j];
        reinterpret_cast<__half2*>(g_Wp)[j] = __floats2half2_rn(v.x, v.y);
    } else if (i < NW12 + NW22 + TOTB) {
        int idx = i - NW12 - NW22;
        int h = idx / (NPR * NP);
        int rem = idx - h * (NPR * NP);
        int r = rem / NP, c = rem - r * NP;
        float v = 0.0f;
        if (r < NN && c < NN) v = tab[ridx[r * NN + c] * HH + h];
        g_bias[idx] = __float2half(v);
    }
}

// ---------------- raw-mma GEMM: 128x128 tile, 8 warps x (32x64) --------------
#define GBK 64
#define NKCH (DIM / GBK)      // 12 chunks
#define GSTG 3
#define GST 72                // row stride in halves
#define OPB (128 * GST * 2)   // 18432 bytes per operand per stage
#define STB (2 * OPB)         // 36864
#define SMEM_G (GSTG * STB)   // 110592

__global__ __launch_bounds__(256, 2)
void gemm_kernel(int mode, const float* __restrict__ bias, float* __restrict__ outf) {
    extern __shared__ __align__(16) char smraw[];

    const __half* A = (mode == 0) ? g_Xh : g_AO;
    const __half* W = (mode == 0) ? g_Wqkv : g_Wp;
    const int m0 = blockIdx.y * 128;
    const int n0 = blockIdx.x * 128;
    const int tid = threadIdx.x, lane = tid & 31, wid = tid >> 5;
    const int wm = wid & 3, wn = wid >> 2;   // 4x2 warps, each 32x64

    const unsigned sbase = smem_u32(smraw);
    auto stA = [&](int s) { return sbase + s * STB; };
    auto stB = [&](int s) { return sbase + s * STB + OPB; };

    float c[2][8][4];
#pragma unroll
    for (int mi = 0; mi < 2; mi++)
#pragma unroll
        for (int ni = 0; ni < 8; ni++)
#pragma unroll
            for (int j = 0; j < 4; j++) c[mi][ni][j] = 0.0f;

    auto prefetch = [&](int kt, int s) {
        const __half* Ab = A + (size_t)m0 * DIM + kt * GBK;
        const __half* Bb = W + (size_t)n0 * DIM + kt * GBK;
        unsigned sa = stA(s), sb = stB(s);
#pragma unroll
        for (int t = tid; t < 1024; t += 256) {
            int r = t >> 3, u = t & 7;
            cpa16s(sa + (r * GST + u * 8) * 2, Ab + (size_t)r * DIM + u * 8);
        }
#pragma unroll
        for (int t = tid; t < 1024; t += 256) {
            int r = t >> 3, u = t & 7;
            cpa16s(sb + (r * GST + u * 8) * 2, Bb + (size_t)r * DIM + u * 8);
        }
    };

    prefetch(0, 0); CP_COMMIT();
    prefetch(1, 1); CP_COMMIT();

    const int la_r = lane & 15, la_k = (lane >> 4) * 8;              // A frags
    const int lb_n = (lane >> 4) * 8 + (lane & 7);                   // B frags
    const int lb_k = ((lane >> 3) & 1) * 8;

    for (int kt = 0; kt < NKCH; kt++) {
        const int s = kt % GSTG;
        if (kt == NKCH - 1) { CP_WAIT(0); } else { CP_WAIT(1); }
        __syncthreads();
        if (kt + 2 < NKCH) {
            prefetch(kt + 2, (kt + 2) % GSTG);
            CP_COMMIT();
        }
        const unsigned sa = stA(s), sb = stB(s);
#pragma unroll
        for (int kk = 0; kk < 4; kk++) {
            unsigned am[2][4];
            unsigned bm[4][4];
#pragma unroll
            for (int mi = 0; mi < 2; mi++)
                ldsm4(am[mi][0], am[mi][1], am[mi][2], am[mi][3],
                      sa + ((wm * 32 + mi * 16 + la_r) * GST + kk * 16 + la_k) * 2);
#pragma unroll
            for (int nt = 0; nt < 4; nt++)
                ldsm4(bm[nt][0], bm[nt][1], bm[nt][2], bm[nt][3],
                      sb + ((wn * 64 + nt * 16 + lb_n) * GST + kk * 16 + lb_k) * 2);
#pragma unroll
            for (int nt = 0; nt < 4; nt++)
#pragma unroll
                for (int mi = 0; mi < 2; mi++) {
                    mma16816(c[mi][2 * nt],     am[mi], bm[nt][0], bm[nt][1]);
                    mma16816(c[mi][2 * nt + 1], am[mi], bm[nt][2], bm[nt][3]);
                }
        }
    }

    // ---- register-direct epilogue ----
    const int qd = lane >> 2, ql = lane & 3;
    const int nbase = n0 + wn * 64;
    if (mode == 1) {
#pragma unroll
        for (int mi = 0; mi < 2; mi++) {
            int mr0 = m0 + wm * 32 + mi * 16 + qd;
            float* d0 = outf + (size_t)mr0 * DIM + nbase;
            float* d1 = d0 + 8 * DIM;
#pragma unroll
            for (int ni = 0; ni < 8; ni++) {
                int col = ni * 8 + ql * 2;
                float2 bv = *reinterpret_cast<const float2*>(bias + nbase + col);
                float2 lo = make_float2(c[mi][ni][0] + bv.x, c[mi][ni][1] + bv.y);
                float2 hi = make_float2(c[mi][ni][2] + bv.x, c[mi][ni][3] + bv.y);
                *reinterpret_cast<float2*>(d0 + col) = lo;
                *reinterpret_cast<float2*>(d1 + col) = hi;
            }
        }
    } else {
        const int which = nbase / DIM;
        const int rem = nbase - which * DIM;
        const int h = rem >> 6;                    // 64-aligned head
        __half* dstB = (which == 0) ? g_Q : (which == 1) ? g_K : g_V;
        const float scl = (which == 0) ? 0.125f : 1.0f;
#pragma unroll
        for (int mi = 0; mi < 2; mi++) {
            int mr0 = m0 + wm * 32 + mi * 16 + qd;
            int mr1 = mr0 + 8;
            int b0r = mr0 / NN, t0 = mr0 - b0r * NN;
            int b1r = mr1 / NN, t1 = mr1 - b1r * NN;
            __half* p0 = dstB + ((size_t)(b0r * HH + h) * NN + t0) * DH;
            __half* p1 = dstB + ((size_t)(b1r * HH + h) * NN + t1) * DH;
#pragma unroll
            for (int ni = 0; ni < 8; ni++) {
                int d = ni * 8 + ql * 2;
                *reinterpret_cast<__half2*>(p0 + d) =
                    __floats2half2_rn(c[mi][ni][0] * scl, c[mi][ni][1] * scl);
                *reinterpret_cast<__half2*>(p1 + d) =
                    __floats2half2_rn(c[mi][ni][2] * scl, c[mi][ni][3] * scl);
            }
        }
    }
}

// ---------------- FA2-style attention: 416 threads, 1 strip per warp ---------
#define ATHR 416
#define SMEM_ATTN (2 * NP * 72 * 2)

__global__ __launch_bounds__(ATHR, 1)
void attn_kernel() {
    extern __shared__ __align__(16) char sm[];
    __half* Ksm = reinterpret_cast<__half*>(sm);
    __half* Vsm = reinterpret_cast<__half*>(sm + NP * 72 * 2);

    const int bh = blockIdx.x;
    const int b = bh / HH, h = bh - b * HH;
    const __half* Kg = g_K + (size_t)bh * NN * DH;
    const __half* Vg = g_V + (size_t)bh * NN * DH;
    const __half* Qg = g_Q + (size_t)bh * NN * DH;
    const __half* biasH = g_bias + (size_t)h * NPR * NP;
    const int tid = threadIdx.x, lane = tid & 31, wid = tid >> 5;

    for (int idx = tid; idx < NP * 8; idx += ATHR) {
        int r = idx >> 3, c = idx & 7;
        uint4 z = make_uint4(0, 0, 0, 0);
        uint4 kv = (r < NN) ? *reinterpret_cast<const uint4*>(&Kg[r * DH + c * 8]) : z;
        uint4 vv = (r < NN) ? *reinterpret_cast<const uint4*>(&Vg[r * DH + c * 8]) : z;
        *reinterpret_cast<uint4*>(&Ksm[r * 72 + c * 8]) = kv;
        *reinterpret_cast<uint4*>(&Vsm[r * 72 + c * 8]) = vv;
    }
    __syncthreads();

    const int qd = lane >> 2;
    const int ql = lane & 3;

    // one strip per warp (13 warps, 13 strips)
    {
        const int strip = wid;
        const int r0 = strip * 16;
        const int row0 = r0 + qd;
        const int row1 = row0 + 8;

        unsigned a[4][4];
        {
            const __half2* Qa = reinterpret_cast<const __half2*>(
                Qg + (size_t)min(row0, NN - 1) * DH);
            const __half2* Qb = reinterpret_cast<const __half2*>(
                Qg + (size_t)min(row1, NN - 1) * DH);
#pragma unroll
            for (int kk = 0; kk < 4; kk++) {
                a[kk][0] = reinterpret_cast<const unsigned*>(Qa)[kk * 8 + ql];
                a[kk][1] = reinterpret_cast<const unsigned*>(Qb)[kk * 8 + ql];
                a[kk][2] = reinterpret_cast<const unsigned*>(Qa)[kk * 8 + 4 + ql];
                a[kk][3] = reinterpret_cast<const unsigned*>(Qb)[kk * 8 + 4 + ql];
            }
        }

        float c[25][4];
#pragma unroll
        for (int nb = 0; nb < 25; nb++) {
            __half2 b0 = *reinterpret_cast<const __half2*>(
                biasH + (size_t)row0 * NP + nb * 8 + ql * 2);
            __half2 b1 = *reinterpret_cast<const __half2*>(
                biasH + (size_t)row1 * NP + nb * 8 + ql * 2);
            float2 f0 = __half22float2(b0);
            float2 f1 = __half22float2(b1);
            c[nb][0] = f0.x; c[nb][1] = f0.y; c[nb][2] = f1.x; c[nb][3] = f1.y;
        }

        const int ln = (lane >> 4) * 8 + (lane & 7);
        const int lk = ((lane >> 3) & 1) * 8;
#pragma unroll
        for (int np = 0; np < 13; np++) {
#pragma unroll
            for (int kk = 0; kk < 4; kk++) {
                unsigned b0, b1, b2, b3;
                ldsm4p(b0, b1, b2, b3, Ksm + (np * 16 + ln) * 72 + kk * 16 + lk);
                mma16816(c[2 * np], a[kk], b0, b1);
                if (np < 12) mma16816(c[2 * np + 1], a[kk], b2, b3);
            }
        }

        {
            int c0 = 192 + ql * 2;
            if (c0 >= NN)     { c[24][0] = -1e30f; c[24][2] = -1e30f; }
            if (c0 + 1 >= NN) { c[24][1] = -1e30f; c[24][3] = -1e30f; }
        }

        float m0 = -1e30f, m1 = -1e30f;
#pragma unroll
        for (int nb = 0; nb < 25; nb++) {
            m0 = fmaxf(m0, fmaxf(c[nb][0], c[nb][1]));
            m1 = fmaxf(m1, fmaxf(c[nb][2], c[nb][3]));
        }
        m0 = fmaxf(m0, __shfl_xor_sync(~0u, m0, 1));
        m0 = fmaxf(m0, __shfl_xor_sync(~0u, m0, 2));
        m1 = fmaxf(m1, __shfl_xor_sync(~0u, m1, 1));
        m1 = fmaxf(m1, __shfl_xor_sync(~0u, m1, 2));

        float s0 = 0.0f, s1 = 0.0f;
        unsigned p[25];
#pragma unroll
        for (int nb = 0; nb < 25; nb++) {
            float e0 = __expf(c[nb][0] - m0);
            float e1 = __expf(c[nb][1] - m0);
            float e2 = __expf(c[nb][2] - m1);
            float e3 = __expf(c[nb][3] - m1);
            s0 += e0 + e1;
            s1 += e2 + e3;
            __half2 lo = __floats2half2_rn(e0, e1);
            __half2 hi = __floats2half2_rn(e2, e3);
            p[nb] = h2_as_u(lo);
            c[nb][2] = __uint_as_float(h2_as_u(hi));
        }
        s0 += __shfl_xor_sync(~0u, s0, 1);
        s0 += __shfl_xor_sync(~0u, s0, 2);
        s1 += __shfl_xor_sync(~0u, s1, 1);
        s1 += __shfl_xor_sync(~0u, s1, 2);
        float rinv0 = 1.0f / s0, rinv1 = 1.0f / s1;

        float o[8][4];
#pragma unroll
        for (int d = 0; d < 8; d++)
#pragma unroll
            for (int j = 0; j < 4; j++) o[d][j] = 0.0f;

        const int lkv = ((lane >> 3) & 1) * 8 + (lane & 7);
        const int ldv = (lane >> 4) * 8;
#pragma unroll
        for (int kc = 0; kc < 13; kc++) {
            unsigned pa[4];
            pa[0] = p[2 * kc];
            pa[1] = __float_as_uint(c[2 * kc][2]);
            if (kc < 12) {
                pa[2] = p[2 * kc + 1];
                pa[3] = __float_as_uint(c[2 * kc + 1][2]);
            } else {
                pa[2] = 0; pa[3] = 0;
            }
#pragma unroll
            for (int dp = 0; dp < 4; dp++) {
                unsigned b0, b1, b2, b3;
                ldsm4t(b0, b1, b2, b3, Vsm + (kc * 16 + lkv) * 72 + dp * 16 + ldv);
                mma16816(o[2 * dp], pa, b0, b1);
                mma16816(o[2 * dp + 1], pa, b2, b3);
            }
        }

        if (row0 < NN) {
            __half2* op = reinterpret_cast<__half2*>(
                g_AO + (size_t)(b * NN + row0) * DIM + h * DH);
#pragma unroll
            for (int d = 0; d < 8; d++)
                op[d * 4 + ql] = __floats2half2_rn(o[d][0] * rinv0, o[d][1] * rinv0);
        }
        if (row1 < NN) {
            __half2* op = reinterpret_cast<__half2*>(
                g_AO + (size_t)(b * NN + row1) * DIM + h * DH);
#pragma unroll
            for (int d = 0; d < 8; d++)
                op[d * 4 + ql] = __floats2half2_rn(o[d][2] * rinv1, o[d][3] * rinv1);
        }
    }
}

// ---------------- launch ----------------
extern "C" void kernel_launch(void* const* d_in, const int* in_sizes, int n_in,
                              void* d_out, int out_size) {
    const float* x     = (const float*)d_in[0];
    const float* qkvw  = (const float*)d_in[1];
    const float* projw = (const float*)d_in[2];
    const float* projb = (const float*)d_in[3];
    const float* btab  = (const float*)d_in[4];
    const int*   ridx  = (const int*)d_in[5];
    float* out = (float*)d_out;

    cudaFuncSetAttribute(attn_kernel, cudaFuncAttributeMaxDynamicSharedMemorySize,
                         SMEM_ATTN);
    cudaFuncSetAttribute(gemm_kernel, cudaFuncAttributeMaxDynamicSharedMemorySize,
                         SMEM_G);

    f2h_x<<<(NX2 + 255) / 256, 256>>>(x);                            // 0
    const int nwb = NW12 + NW22 + TOTB;
    f2h_wb<<<(nwb + 255) / 256, 256>>>(qkvw, projw, btab, ridx);     // 1

    // QKV: M=25216 (197 tiles), N=2304 (18 tiles)                    // 2
    gemm_kernel<<<dim3(18, 197), 256, SMEM_G>>>(0, nullptr, nullptr);

    attn_kernel<<<BB * HH, ATHR, SMEM_ATTN>>>();                     // 3 (profiled)

    // proj: N=768 (6 tiles)                                          // 4
    gemm_kernel<<<dim3(6, 197), 256, SMEM_G>>>(1, projb, out);
}

// round 16
// speedup vs baseline: 1.0287x; 1.0287x over previous
#include <cuda_runtime.h>
#include <cuda_fp16.h>
#include <cstdint>

// Problem constants
#define BB   128
#define HH   12
#define DH   64
#define DIM  768
#define NN   197
#define MTOT (BB * NN)          // 25216 = 197 * 128
#define TABLE 730
#define NP   208                // padded cols for bias / S
#define NPR  256                // padded rows for bias
#define LOG2E 1.4426950408889634f

// ---------------- scratch (device globals; no allocations allowed) ----------
__device__ alignas(16) __half g_Xh[(size_t)MTOT * DIM];
__device__ alignas(16) __half g_Wqkv[(size_t)3 * DIM * DIM];
__device__ alignas(16) __half g_Wp[(size_t)DIM * DIM];
__device__ alignas(16) __half g_Q[(size_t)BB * HH * NN * DH];   // scaled by 0.125*log2e
__device__ alignas(16) __half g_K[(size_t)BB * HH * NN * DH];
__device__ alignas(16) __half g_V[(size_t)BB * HH * NN * DH];
__device__ alignas(16) __half g_AO[(size_t)MTOT * DIM];
__device__ alignas(16) __half g_bias[(size_t)HH * NPR * NP];    // fp16 bias * log2e

// ---------------- helpers ----------------
__device__ __forceinline__ unsigned smem_u32(const void* p) {
    return (unsigned)__cvta_generic_to_shared(p);
}
__device__ __forceinline__ unsigned h2_as_u(__half2 h) {
    return *reinterpret_cast<unsigned*>(&h);
}
__device__ __forceinline__ void cpa16s(unsigned sdst, const void* src) {
    asm volatile("cp.async.cg.shared.global [%0], [%1], 16;" :: "r"(sdst), "l"(src));
}
#define CP_COMMIT() asm volatile("cp.async.commit_group;")
#define CP_WAIT(n)  asm volatile("cp.async.wait_group %0;" :: "n"(n))

__device__ __forceinline__ void ldsm4(unsigned& r0, unsigned& r1, unsigned& r2,
                                      unsigned& r3, unsigned a) {
    asm volatile("ldmatrix.sync.aligned.m8n8.x4.shared.b16 {%0,%1,%2,%3}, [%4];"
                 : "=r"(r0), "=r"(r1), "=r"(r2), "=r"(r3) : "r"(a));
}
__device__ __forceinline__ void ldsm4p(unsigned& r0, unsigned& r1, unsigned& r2,
                                       unsigned& r3, const void* p) {
    ldsm4(r0, r1, r2, r3, smem_u32(p));
}
__device__ __forceinline__ void ldsm4t(unsigned& r0, unsigned& r1, unsigned& r2,
                                       unsigned& r3, const void* p) {
    unsigned a = smem_u32(p);
    asm volatile("ldmatrix.sync.aligned.m8n8.x4.trans.shared.b16 {%0,%1,%2,%3}, [%4];"
                 : "=r"(r0), "=r"(r1), "=r"(r2), "=r"(r3) : "r"(a));
}
__device__ __forceinline__ void mma16816(float* c, const unsigned* a,
                                         unsigned b0, unsigned b1) {
    asm volatile(
        "mma.sync.aligned.m16n8k16.row.col.f32.f16.f16.f32 "
        "{%0,%1,%2,%3}, {%4,%5,%6,%7}, {%8,%9}, {%0,%1,%2,%3};"
        : "+f"(c[0]), "+f"(c[1]), "+f"(c[2]), "+f"(c[3])
        : "r"(a[0]), "r"(a[1]), "r"(a[2]), "r"(a[3]), "r"(b0), "r"(b1));
}

// ---------------- single fused prep kernel -----------------------------------
#define NX2  (MTOT * DIM / 2)
#define NW12 (3 * DIM * DIM / 2)
#define NW22 (DIM * DIM / 2)
#define TOTB (HH * NPR * NP)
#define NPREP (NX2 + NW12 + NW22 + TOTB)

__global__ void prep_all(const float* __restrict__ x, const float* __restrict__ qkvw,
                         const float* __restrict__ projw, const float* __restrict__ tab,
                         const int* __restrict__ ridx) {
    int i = blockIdx.x * blockDim.x + threadIdx.x;
    if (i < NX2) {
        float2 v = reinterpret_cast<const float2*>(x)[i];
        reinterpret_cast<__half2*>(g_Xh)[i] = __floats2half2_rn(v.x, v.y);
    } else if (i < NX2 + NW12) {
        int j = i - NX2;
        float2 v = reinterpret_cast<const float2*>(qkvw)[j];
        reinterpret_cast<__half2*>(g_Wqkv)[j] = __floats2half2_rn(v.x, v.y);
    } else if (i < NX2 + NW12 + NW22) {
        int j = i - NX2 - NW12;
        float2 v = reinterpret_cast<const float2*>(projw)[j];
        reinterpret_cast<__half2*>(g_Wp)[j] = __floats2half2_rn(v.x, v.y);
    } else if (i < NPREP) {
        int idx = i - NX2 - NW12 - NW22;
        int h = idx / (NPR * NP);
        int rem = idx - h * (NPR * NP);
        int r = rem / NP, c = rem - r * NP;
        float v = 0.0f;
        if (r < NN && c < NN) v = tab[ridx[r * NN + c] * HH + h] * LOG2E;
        g_bias[idx] = __float2half(v);
    }
}

// ---------------- raw-mma GEMM: 128x128 tile, 8 warps x (32x64) --------------
#define GBK 64
#define NKCH (DIM / GBK)      // 12 chunks
#define GSTG 3
#define GST 72                // row stride in halves
#define OPB (128 * GST * 2)   // 18432 bytes per operand per stage
#define STB (2 * OPB)         // 36864
#define SMEM_G (GSTG * STB)   // 110592

__global__ __launch_bounds__(256, 2)
void gemm_kernel(int mode, const float* __restrict__ bias, float* __restrict__ outf) {
    extern __shared__ __align__(16) char smraw[];

    const __half* A = (mode == 0) ? g_Xh : g_AO;
    const __half* W = (mode == 0) ? g_Wqkv : g_Wp;
    const int m0 = blockIdx.y * 128;
    const int n0 = blockIdx.x * 128;
    const int tid = threadIdx.x, lane = tid & 31, wid = tid >> 5;
    const int wm = wid & 3, wn = wid >> 2;   // 4x2 warps, each 32x64

    const unsigned sbase = smem_u32(smraw);
    auto stA = [&](int s) { return sbase + s * STB; };
    auto stB = [&](int s) { return sbase + s * STB + OPB; };

    float c[2][8][4];
#pragma unroll
    for (int mi = 0; mi < 2; mi++)
#pragma unroll
        for (int ni = 0; ni < 8; ni++)
#pragma unroll
            for (int j = 0; j < 4; j++) c[mi][ni][j] = 0.0f;

    auto prefetch = [&](int kt, int s) {
        const __half* Ab = A + (size_t)m0 * DIM + kt * GBK;
        const __half* Bb = W + (size_t)n0 * DIM + kt * GBK;
        unsigned sa = stA(s), sb = stB(s);
#pragma unroll
        for (int t = tid; t < 1024; t += 256) {
            int r = t >> 3, u = t & 7;
            cpa16s(sa + (r * GST + u * 8) * 2, Ab + (size_t)r * DIM + u * 8);
        }
#pragma unroll
        for (int t = tid; t < 1024; t += 256) {
            int r = t >> 3, u = t & 7;
            cpa16s(sb + (r * GST + u * 8) * 2, Bb + (size_t)r * DIM + u * 8);
        }
    };

    prefetch(0, 0); CP_COMMIT();
    prefetch(1, 1); CP_COMMIT();

    const int la_r = lane & 15, la_k = (lane >> 4) * 8;              // A frags
    const int lb_n = (lane >> 4) * 8 + (lane & 7);                   // B frags
    const int lb_k = ((lane >> 3) & 1) * 8;

    for (int kt = 0; kt < NKCH; kt++) {
        const int s = kt % GSTG;
        if (kt == NKCH - 1) { CP_WAIT(0); } else { CP_WAIT(1); }
        __syncthreads();
        if (kt + 2 < NKCH) {
            prefetch(kt + 2, (kt + 2) % GSTG);
            CP_COMMIT();
        }
        const unsigned sa = stA(s), sb = stB(s);
#pragma unroll
        for (int kk = 0; kk < 4; kk++) {
            unsigned am[2][4];
            unsigned bm[4][4];
#pragma unroll
            for (int mi = 0; mi < 2; mi++)
                ldsm4(am[mi][0], am[mi][1], am[mi][2], am[mi][3],
                      sa + ((wm * 32 + mi * 16 + la_r) * GST + kk * 16 + la_k) * 2);
#pragma unroll
            for (int nt = 0; nt < 4; nt++)
                ldsm4(bm[nt][0], bm[nt][1], bm[nt][2], bm[nt][3],
                      sb + ((wn * 64 + nt * 16 + lb_n) * GST + kk * 16 + lb_k) * 2);
#pragma unroll
            for (int nt = 0; nt < 4; nt++)
#pragma unroll
                for (int mi = 0; mi < 2; mi++) {
                    mma16816(c[mi][2 * nt],     am[mi], bm[nt][0], bm[nt][1]);
                    mma16816(c[mi][2 * nt + 1], am[mi], bm[nt][2], bm[nt][3]);
                }
        }
    }

    // ---- register-direct epilogue ----
    const int qd = lane >> 2, ql = lane & 3;
    const int nbase = n0 + wn * 64;
    if (mode == 1) {
#pragma unroll
        for (int mi = 0; mi < 2; mi++) {
            int mr0 = m0 + wm * 32 + mi * 16 + qd;
            float* d0 = outf + (size_t)mr0 * DIM + nbase;
            float* d1 = d0 + 8 * DIM;
#pragma unroll
            for (int ni = 0; ni < 8; ni++) {
                int col = ni * 8 + ql * 2;
                float2 bv = *reinterpret_cast<const float2*>(bias + nbase + col);
                float2 lo = make_float2(c[mi][ni][0] + bv.x, c[mi][ni][1] + bv.y);
                float2 hi = make_float2(c[mi][ni][2] + bv.x, c[mi][ni][3] + bv.y);
                *reinterpret_cast<float2*>(d0 + col) = lo;
                *reinterpret_cast<float2*>(d1 + col) = hi;
            }
        }
    } else {
        const int which = nbase / DIM;
        const int rem = nbase - which * DIM;
        const int h = rem >> 6;                    // 64-aligned head
        __half* dstB = (which == 0) ? g_Q : (which == 1) ? g_K : g_V;
        const float scl = (which == 0) ? 0.125f * LOG2E : 1.0f;
#pragma unroll
        for (int mi = 0; mi < 2; mi++) {
            int mr0 = m0 + wm * 32 + mi * 16 + qd;
            int mr1 = mr0 + 8;
            int b0r = mr0 / NN, t0 = mr0 - b0r * NN;
            int b1r = mr1 / NN, t1 = mr1 - b1r * NN;
            __half* p0 = dstB + ((size_t)(b0r * HH + h) * NN + t0) * DH;
            __half* p1 = dstB + ((size_t)(b1r * HH + h) * NN + t1) * DH;
#pragma unroll
            for (int ni = 0; ni < 8; ni++) {
                int d = ni * 8 + ql * 2;
                *reinterpret_cast<__half2*>(p0 + d) =
                    __floats2half2_rn(c[mi][ni][0] * scl, c[mi][ni][1] * scl);
                *reinterpret_cast<__half2*>(p1 + d) =
                    __floats2half2_rn(c[mi][ni][2] * scl, c[mi][ni][3] * scl);
            }
        }
    }
}

// ---------------- FA2-style attention: 160 threads (5 warps), 2 CTAs/SM ------
// S is computed in log2-domain (Q and bias pre-scaled by log2e); softmax uses exp2.
#define ATHR 160
#define SMEM_ATTN (2 * NP * 72 * 2)

__global__ __launch_bounds__(ATHR, 2)
void attn_kernel() {
    extern __shared__ __align__(16) char sm[];
    __half* Ksm = reinterpret_cast<__half*>(sm);
    __half* Vsm = reinterpret_cast<__half*>(sm + NP * 72 * 2);

    const int bh = blockIdx.x;
    const int b = bh / HH, h = bh - b * HH;
    const __half* Kg = g_K + (size_t)bh * NN * DH;
    const __half* Vg = g_V + (size_t)bh * NN * DH;
    const __half* Qg = g_Q + (size_t)bh * NN * DH;
    const __half* biasH = g_bias + (size_t)h * NPR * NP;
    const int tid = threadIdx.x, lane = tid & 31, wid = tid >> 5;

    for (int idx = tid; idx < NP * 8; idx += ATHR) {
        int r = idx >> 3, c = idx & 7;
        uint4 z = make_uint4(0, 0, 0, 0);
        uint4 kv = (r < NN) ? *reinterpret_cast<const uint4*>(&Kg[r * DH + c * 8]) : z;
        uint4 vv = (r < NN) ? *reinterpret_cast<const uint4*>(&Vg[r * DH + c * 8]) : z;
        *reinterpret_cast<uint4*>(&Ksm[r * 72 + c * 8]) = kv;
        *reinterpret_cast<uint4*>(&Vsm[r * 72 + c * 8]) = vv;
    }
    __syncthreads();

    const int qd = lane >> 2;
    const int ql = lane & 3;

    for (int strip = wid; strip < 13; strip += 5) {
        const int r0 = strip * 16;
        const int row0 = r0 + qd;
        const int row1 = row0 + 8;

        unsigned a[4][4];
        {
            const __half2* Qa = reinterpret_cast<const __half2*>(
                Qg + (size_t)min(row0, NN - 1) * DH);
            const __half2* Qb = reinterpret_cast<const __half2*>(
                Qg + (size_t)min(row1, NN - 1) * DH);
#pragma unroll
            for (int kk = 0; kk < 4; kk++) {
                a[kk][0] = reinterpret_cast<const unsigned*>(Qa)[kk * 8 + ql];
                a[kk][1] = reinterpret_cast<const unsigned*>(Qb)[kk * 8 + ql];
                a[kk][2] = reinterpret_cast<const unsigned*>(Qa)[kk * 8 + 4 + ql];
                a[kk][3] = reinterpret_cast<const unsigned*>(Qb)[kk * 8 + 4 + ql];
            }
        }

        float c[25][4];
#pragma unroll
        for (int nb = 0; nb < 25; nb++) {
            __half2 b0 = *reinterpret_cast<const __half2*>(
                biasH + (size_t)row0 * NP + nb * 8 + ql * 2);
            __half2 b1 = *reinterpret_cast<const __half2*>(
                biasH + (size_t)row1 * NP + nb * 8 + ql * 2);
            float2 f0 = __half22float2(b0);
            float2 f1 = __half22float2(b1);
            c[nb][0] = f0.x; c[nb][1] = f0.y; c[nb][2] = f1.x; c[nb][3] = f1.y;
        }

        const int ln = (lane >> 4) * 8 + (lane & 7);
        const int lk = ((lane >> 3) & 1) * 8;
#pragma unroll
        for (int np = 0; np < 13; np++) {
#pragma unroll
            for (int kk = 0; kk < 4; kk++) {
                unsigned b0, b1, b2, b3;
                ldsm4p(b0, b1, b2, b3, Ksm + (np * 16 + ln) * 72 + kk * 16 + lk);
                mma16816(c[2 * np], a[kk], b0, b1);
                if (np < 12) mma16816(c[2 * np + 1], a[kk], b2, b3);
            }
        }

        {
            int c0 = 192 + ql * 2;
            if (c0 >= NN)     { c[24][0] = -1e30f; c[24][2] = -1e30f; }
            if (c0 + 1 >= NN) { c[24][1] = -1e30f; c[24][3] = -1e30f; }
        }

        float m0 = -1e30f, m1 = -1e30f;
#pragma unroll
        for (int nb = 0; nb < 25; nb++) {
            m0 = fmaxf(m0, fmaxf(c[nb][0], c[nb][1]));
            m1 = fmaxf(m1, fmaxf(c[nb][2], c[nb][3]));
        }
        m0 = fmaxf(m0, __shfl_xor_sync(~0u, m0, 1));
        m0 = fmaxf(m0, __shfl_xor_sync(~0u, m0, 2));
        m1 = fmaxf(m1, __shfl_xor_sync(~0u, m1, 1));
        m1 = fmaxf(m1, __shfl_xor_sync(~0u, m1, 2));

        float s0 = 0.0f, s1 = 0.0f;
        unsigned p[25];
#pragma unroll
        for (int nb = 0; nb < 25; nb++) {
            float e0 = exp2f(c[nb][0] - m0);
            float e1 = exp2f(c[nb][1] - m0);
            float e2 = exp2f(c[nb][2] - m1);
            float e3 = exp2f(c[nb][3] - m1);
            s0 += e0 + e1;
            s1 += e2 + e3;
            __half2 lo = __floats2half2_rn(e0, e1);
            __half2 hi = __floats2half2_rn(e2, e3);
            p[nb] = h2_as_u(lo);
            c[nb][2] = __uint_as_float(h2_as_u(hi));
        }
        s0 += __shfl_xor_sync(~0u, s0, 1);
        s0 += __shfl_xor_sync(~0u, s0, 2);
        s1 += __shfl_xor_sync(~0u, s1, 1);
        s1 += __shfl_xor_sync(~0u, s1, 2);
        float rinv0 = 1.0f / s0, rinv1 = 1.0f / s1;

        float o[8][4];
#pragma unroll
        for (int d = 0; d < 8; d++)
#pragma unroll
            for (int j = 0; j < 4; j++) o[d][j] = 0.0f;

        const int lkv = ((lane >> 3) & 1) * 8 + (lane & 7);
        const int ldv = (lane >> 4) * 8;
#pragma unroll
        for (int kc = 0; kc < 13; kc++) {
            unsigned pa[4];
            pa[0] = p[2 * kc];
            pa[1] = __float_as_uint(c[2 * kc][2]);
            if (kc < 12) {
                pa[2] = p[2 * kc + 1];
                pa[3] = __float_as_uint(c[2 * kc + 1][2]);
            } else {
                pa[2] = 0; pa[3] = 0;
            }
#pragma unroll
            for (int dp = 0; dp < 4; dp++) {
                unsigned b0, b1, b2, b3;
                ldsm4t(b0, b1, b2, b3, Vsm + (kc * 16 + lkv) * 72 + dp * 16 + ldv);
                mma16816(o[2 * dp], pa, b0, b1);
                mma16816(o[2 * dp + 1], pa, b2, b3);
            }
        }

        if (row0 < NN) {
            __half2* op = reinterpret_cast<__half2*>(
                g_AO + (size_t)(b * NN + row0) * DIM + h * DH);
#pragma unroll
            for (int d = 0; d < 8; d++)
                op[d * 4 + ql] = __floats2half2_rn(o[d][0] * rinv0, o[d][1] * rinv0);
        }
        if (row1 < NN) {
            __half2* op = reinterpret_cast<__half2*>(
                g_AO + (size_t)(b * NN + row1) * DIM + h * DH);
#pragma unroll
            for (int d = 0; d < 8; d++)
                op[d * 4 + ql] = __floats2half2_rn(o[d][2] * rinv1, o[d][3] * rinv1);
        }
    }
}

// ---------------- launch ----------------
extern "C" void kernel_launch(void* const* d_in, const int* in_sizes, int n_in,
                              void* d_out, int out_size) {
    const float* x     = (const float*)d_in[0];
    const float* qkvw  = (const float*)d_in[1];
    const float* projw = (const float*)d_in[2];
    const float* projb = (const float*)d_in[3];
    const float* btab  = (const float*)d_in[4];
    const int*   ridx  = (const int*)d_in[5];
    float* out = (float*)d_out;

    cudaFuncSetAttribute(attn_kernel, cudaFuncAttributeMaxDynamicSharedMemorySize,
                         SMEM_ATTN);
    cudaFuncSetAttribute(gemm_kernel, cudaFuncAttributeMaxDynamicSharedMemorySize,
                         SMEM_G);

    prep_all<<<(NPREP + 255) / 256, 256>>>(x, qkvw, projw, btab, ridx);  // 0

    // QKV: M=25216 (197 tiles), N=2304 (18 tiles)                        // 1
    gemm_kernel<<<dim3(18, 197), 256, SMEM_G>>>(0, nullptr, nullptr);

    attn_kernel<<<BB * HH, ATHR, SMEM_ATTN>>>();                         // 2

    // proj: N=768 (6 tiles)                                              // 3 (profiled)
    gemm_kernel<<<dim3(6, 197), 256, SMEM_G>>>(1, projb, out);
}

// round 17
// speedup vs baseline: 1.0474x; 1.0181x over previous
#include <cuda_runtime.h>
#include <cuda_fp16.h>
#include <cstdint>

// Problem constants
#define BB   128
#define HH   12
#define DH   64
#define DIM  768
#define NN   197
#define MTOT (BB * NN)          // 25216 = 197 * 128
#define TABLE 730
#define NP   208                // padded cols for bias / S
#define NPR  256                // padded rows for bias
#define LOG2E 1.4426950408889634f

// ---------------- scratch (device globals; no allocations allowed) ----------
__device__ alignas(16) __half g_Xh[(size_t)MTOT * DIM];
__device__ alignas(16) __half g_Wqkv[(size_t)3 * DIM * DIM];
__device__ alignas(16) __half g_Wp[(size_t)DIM * DIM];
__device__ alignas(16) __half g_Q[(size_t)BB * HH * NN * DH];   // scaled by 0.125*log2e
__device__ alignas(16) __half g_K[(size_t)BB * HH * NN * DH];
__device__ alignas(16) __half g_V[(size_t)BB * HH * NN * DH];
__device__ alignas(16) __half g_AO[(size_t)MTOT * DIM];
__device__ alignas(16) __half g_bias[(size_t)HH * NPR * NP];    // fp16 bias * log2e

// ---------------- helpers ----------------
__device__ __forceinline__ unsigned smem_u32(const void* p) {
    return (unsigned)__cvta_generic_to_shared(p);
}
__device__ __forceinline__ unsigned h2_as_u(__half2 h) {
    return *reinterpret_cast<unsigned*>(&h);
}
__device__ __forceinline__ void cpa16s(unsigned sdst, const void* src) {
    asm volatile("cp.async.cg.shared.global [%0], [%1], 16;" :: "r"(sdst), "l"(src));
}
#define CP_COMMIT() asm volatile("cp.async.commit_group;")
#define CP_WAIT(n)  asm volatile("cp.async.wait_group %0;" :: "n"(n))

__device__ __forceinline__ void ldsm4(unsigned& r0, unsigned& r1, unsigned& r2,
                                      unsigned& r3, unsigned a) {
    asm volatile("ldmatrix.sync.aligned.m8n8.x4.shared.b16 {%0,%1,%2,%3}, [%4];"
                 : "=r"(r0), "=r"(r1), "=r"(r2), "=r"(r3) : "r"(a));
}
__device__ __forceinline__ void ldsm4p(unsigned& r0, unsigned& r1, unsigned& r2,
                                       unsigned& r3, const void* p) {
    ldsm4(r0, r1, r2, r3, smem_u32(p));
}
__device__ __forceinline__ void ldsm4t(unsigned& r0, unsigned& r1, unsigned& r2,
                                       unsigned& r3, const void* p) {
    unsigned a = smem_u32(p);
    asm volatile("ldmatrix.sync.aligned.m8n8.x4.trans.shared.b16 {%0,%1,%2,%3}, [%4];"
                 : "=r"(r0), "=r"(r1), "=r"(r2), "=r"(r3) : "r"(a));
}
__device__ __forceinline__ void mma16816(float* c, const unsigned* a,
                                         unsigned b0, unsigned b1) {
    asm volatile(
        "mma.sync.aligned.m16n8k16.row.col.f32.f16.f16.f32 "
        "{%0,%1,%2,%3}, {%4,%5,%6,%7}, {%8,%9}, {%0,%1,%2,%3};"
        : "+f"(c[0]), "+f"(c[1]), "+f"(c[2]), "+f"(c[3])
        : "r"(a[0]), "r"(a[1]), "r"(a[2]), "r"(a[3]), "r"(b0), "r"(b1));
}

// ---------------- single fused prep kernel (float4 vectorized) ---------------
#define NX4  (MTOT * DIM / 4)
#define NW14 (3 * DIM * DIM / 4)
#define NW24 (DIM * DIM / 4)
#define TOTB (HH * NPR * NP)
#define NPREP (NX4 + NW14 + NW24 + TOTB)

__device__ __forceinline__ void cvt4(__half2* dst, const float4 v) {
    dst[0] = __floats2half2_rn(v.x, v.y);
    dst[1] = __floats2half2_rn(v.z, v.w);
}

__global__ void prep_all(const float* __restrict__ x, const float* __restrict__ qkvw,
                         const float* __restrict__ projw, const float* __restrict__ tab,
                         const int* __restrict__ ridx) {
    int i = blockIdx.x * blockDim.x + threadIdx.x;
    if (i < NX4) {
        float4 v = reinterpret_cast<const float4*>(x)[i];
        cvt4(reinterpret_cast<__half2*>(g_Xh) + i * 2, v);
    } else if (i < NX4 + NW14) {
        int j = i - NX4;
        float4 v = reinterpret_cast<const float4*>(qkvw)[j];
        cvt4(reinterpret_cast<__half2*>(g_Wqkv) + j * 2, v);
    } else if (i < NX4 + NW14 + NW24) {
        int j = i - NX4 - NW14;
        float4 v = reinterpret_cast<const float4*>(projw)[j];
        cvt4(reinterpret_cast<__half2*>(g_Wp) + j * 2, v);
    } else if (i < NPREP) {
        int idx = i - NX4 - NW14 - NW24;
        int h = idx / (NPR * NP);
        int rem = idx - h * (NPR * NP);
        int r = rem / NP, c = rem - r * NP;
        float v = 0.0f;
        if (r < NN && c < NN) v = tab[ridx[r * NN + c] * HH + h] * LOG2E;
        g_bias[idx] = __float2half(v);
    }
}

// ---------------- raw-mma GEMM: 128x128 tile, 8 warps x (32x64) --------------
#define GBK 64
#define NKCH (DIM / GBK)      // 12 chunks
#define GSTG 3
#define GST 72                // row stride in halves
#define OPB (128 * GST * 2)   // 18432 bytes per operand per stage
#define STB (2 * OPB)         // 36864
#define SMEM_G (GSTG * STB)   // 110592

__global__ __launch_bounds__(256, 2)
void gemm_kernel(int mode, const float* __restrict__ bias, float* __restrict__ outf) {
    extern __shared__ __align__(16) char smraw[];

    const __half* A = (mode == 0) ? g_Xh : g_AO;
    const __half* W = (mode == 0) ? g_Wqkv : g_Wp;
    const int m0 = blockIdx.y * 128;
    const int n0 = blockIdx.x * 128;
    const int tid = threadIdx.x, lane = tid & 31, wid = tid >> 5;
    const int wm = wid & 3, wn = wid >> 2;   // 4x2 warps, each 32x64

    const unsigned sbase = smem_u32(smraw);
    auto stA = [&](int s) { return sbase + s * STB; };
    auto stB = [&](int s) { return sbase + s * STB + OPB; };

    float c[2][8][4];
#pragma unroll
    for (int mi = 0; mi < 2; mi++)
#pragma unroll
        for (int ni = 0; ni < 8; ni++)
#pragma unroll
            for (int j = 0; j < 4; j++) c[mi][ni][j] = 0.0f;

    auto prefetch = [&](int kt, int s) {
        const __half* Ab = A + (size_t)m0 * DIM + kt * GBK;
        const __half* Bb = W + (size_t)n0 * DIM + kt * GBK;
        unsigned sa = stA(s), sb = stB(s);
#pragma unroll
        for (int t = tid; t < 1024; t += 256) {
            int r = t >> 3, u = t & 7;
            cpa16s(sa + (r * GST + u * 8) * 2, Ab + (size_t)r * DIM + u * 8);
        }
#pragma unroll
        for (int t = tid; t < 1024; t += 256) {
            int r = t >> 3, u = t & 7;
            cpa16s(sb + (r * GST + u * 8) * 2, Bb + (size_t)r * DIM + u * 8);
        }
    };

    prefetch(0, 0); CP_COMMIT();
    prefetch(1, 1); CP_COMMIT();

    const int la_r = lane & 15, la_k = (lane >> 4) * 8;              // A frags
    const int lb_n = (lane >> 4) * 8 + (lane & 7);                   // B frags
    const int lb_k = ((lane >> 3) & 1) * 8;

    for (int kt = 0; kt < NKCH; kt++) {
        const int s = kt % GSTG;
        if (kt == NKCH - 1) { CP_WAIT(0); } else { CP_WAIT(1); }
        __syncthreads();
        if (kt + 2 < NKCH) {
            prefetch(kt + 2, (kt + 2) % GSTG);
            CP_COMMIT();
        }
        const unsigned sa = stA(s), sb = stB(s);
#pragma unroll
        for (int kk = 0; kk < 4; kk++) {
            unsigned am[2][4];
            unsigned bm[4][4];
#pragma unroll
            for (int mi = 0; mi < 2; mi++)
                ldsm4(am[mi][0], am[mi][1], am[mi][2], am[mi][3],
                      sa + ((wm * 32 + mi * 16 + la_r) * GST + kk * 16 + la_k) * 2);
#pragma unroll
            for (int nt = 0; nt < 4; nt++)
                ldsm4(bm[nt][0], bm[nt][1], bm[nt][2], bm[nt][3],
                      sb + ((wn * 64 + nt * 16 + lb_n) * GST + kk * 16 + lb_k) * 2);
#pragma unroll
            for (int nt = 0; nt < 4; nt++)
#pragma unroll
                for (int mi = 0; mi < 2; mi++) {
                    mma16816(c[mi][2 * nt],     am[mi], bm[nt][0], bm[nt][1]);
                    mma16816(c[mi][2 * nt + 1], am[mi], bm[nt][2], bm[nt][3]);
                }
        }
    }

    // ---- register-direct epilogue ----
    const int qd = lane >> 2, ql = lane & 3;
    const int nbase = n0 + wn * 64;
    if (mode == 1) {
#pragma unroll
        for (int mi = 0; mi < 2; mi++) {
            int mr0 = m0 + wm * 32 + mi * 16 + qd;
            float* d0 = outf + (size_t)mr0 * DIM + nbase;
            float* d1 = d0 + 8 * DIM;
#pragma unroll
            for (int ni = 0; ni < 8; ni++) {
                int col = ni * 8 + ql * 2;
                float2 bv = *reinterpret_cast<const float2*>(bias + nbase + col);
                float2 lo = make_float2(c[mi][ni][0] + bv.x, c[mi][ni][1] + bv.y);
                float2 hi = make_float2(c[mi][ni][2] + bv.x, c[mi][ni][3] + bv.y);
                *reinterpret_cast<float2*>(d0 + col) = lo;
                *reinterpret_cast<float2*>(d1 + col) = hi;
            }
        }
    } else {
        const int which = nbase / DIM;
        const int rem = nbase - which * DIM;
        const int h = rem >> 6;                    // 64-aligned head
        __half* dstB = (which == 0) ? g_Q : (which == 1) ? g_K : g_V;
        const float scl = (which == 0) ? 0.125f * LOG2E : 1.0f;
#pragma unroll
        for (int mi = 0; mi < 2; mi++) {
            int mr0 = m0 + wm * 32 + mi * 16 + qd;
            int mr1 = mr0 + 8;
            int b0r = mr0 / NN, t0 = mr0 - b0r * NN;
            int b1r = mr1 / NN, t1 = mr1 - b1r * NN;
            __half* p0 = dstB + ((size_t)(b0r * HH + h) * NN + t0) * DH;
            __half* p1 = dstB + ((size_t)(b1r * HH + h) * NN + t1) * DH;
#pragma unroll
            for (int ni = 0; ni < 8; ni++) {
                int d = ni * 8 + ql * 2;
                *reinterpret_cast<__half2*>(p0 + d) =
                    __floats2half2_rn(c[mi][ni][0] * scl, c[mi][ni][1] * scl);
                *reinterpret_cast<__half2*>(p1 + d) =
                    __floats2half2_rn(c[mi][ni][2] * scl, c[mi][ni][3] * scl);
            }
        }
    }
}

// ---------------- FA2-style attention: 192 threads (6 warps), 2 CTAs/SM ------
// S computed in log2-domain (Q and bias pre-scaled by log2e); softmax uses exp2.
#define ATHR 192
#define SMEM_ATTN (2 * NP * 72 * 2)

__global__ __launch_bounds__(ATHR, 2)
void attn_kernel() {
    extern __shared__ __align__(16) char sm[];
    __half* Ksm = reinterpret_cast<__half*>(sm);
    __half* Vsm = reinterpret_cast<__half*>(sm + NP * 72 * 2);

    const int bh = blockIdx.x;
    const int b = bh / HH, h = bh - b * HH;
    const __half* Kg = g_K + (size_t)bh * NN * DH;
    const __half* Vg = g_V + (size_t)bh * NN * DH;
    const __half* Qg = g_Q + (size_t)bh * NN * DH;
    const __half* biasH = g_bias + (size_t)h * NPR * NP;
    const int tid = threadIdx.x, lane = tid & 31, wid = tid >> 5;

    for (int idx = tid; idx < NP * 8; idx += ATHR) {
        int r = idx >> 3, c = idx & 7;
        uint4 z = make_uint4(0, 0, 0, 0);
        uint4 kv = (r < NN) ? *reinterpret_cast<const uint4*>(&Kg[r * DH + c * 8]) : z;
        uint4 vv = (r < NN) ? *reinterpret_cast<const uint4*>(&Vg[r * DH + c * 8]) : z;
        *reinterpret_cast<uint4*>(&Ksm[r * 72 + c * 8]) = kv;
        *reinterpret_cast<uint4*>(&Vsm[r * 72 + c * 8]) = vv;
    }
    __syncthreads();

    const int qd = lane >> 2;
    const int ql = lane & 3;

    for (int strip = wid; strip < 13; strip += 6) {
        const int r0 = strip * 16;
        const int row0 = r0 + qd;
        const int row1 = row0 + 8;

        unsigned a[4][4];
        {
            const __half2* Qa = reinterpret_cast<const __half2*>(
                Qg + (size_t)min(row0, NN - 1) * DH);
            const __half2* Qb = reinterpret_cast<const __half2*>(
                Qg + (size_t)min(row1, NN - 1) * DH);
#pragma unroll
            for (int kk = 0; kk < 4; kk++) {
                a[kk][0] = reinterpret_cast<const unsigned*>(Qa)[kk * 8 + ql];
                a[kk][1] = reinterpret_cast<const unsigned*>(Qb)[kk * 8 + ql];
                a[kk][2] = reinterpret_cast<const unsigned*>(Qa)[kk * 8 + 4 + ql];
                a[kk][3] = reinterpret_cast<const unsigned*>(Qb)[kk * 8 + 4 + ql];
            }
        }

        float c[25][4];
#pragma unroll
        for (int nb = 0; nb < 25; nb++) {
            __half2 b0 = *reinterpret_cast<const __half2*>(
                biasH + (size_t)row0 * NP + nb * 8 + ql * 2);
            __half2 b1 = *reinterpret_cast<const __half2*>(
                biasH + (size_t)row1 * NP + nb * 8 + ql * 2);
            float2 f0 = __half22float2(b0);
            float2 f1 = __half22float2(b1);
            c[nb][0] = f0.x; c[nb][1] = f0.y; c[nb][2] = f1.x; c[nb][3] = f1.y;
        }

        const int ln = (lane >> 4) * 8 + (lane & 7);
        const int lk = ((lane >> 3) & 1) * 8;
#pragma unroll
        for (int np = 0; np < 13; np++) {
#pragma unroll
            for (int kk = 0; kk < 4; kk++) {
                unsigned b0, b1, b2, b3;
                ldsm4p(b0, b1, b2, b3, Ksm + (np * 16 + ln) * 72 + kk * 16 + lk);
                mma16816(c[2 * np], a[kk], b0, b1);
                if (np < 12) mma16816(c[2 * np + 1], a[kk], b2, b3);
            }
        }

        {
            int c0 = 192 + ql * 2;
            if (c0 >= NN)     { c[24][0] = -1e30f; c[24][2] = -1e30f; }
            if (c0 + 1 >= NN) { c[24][1] = -1e30f; c[24][3] = -1e30f; }
        }

        float m0 = -1e30f, m1 = -1e30f;
#pragma unroll
        for (int nb = 0; nb < 25; nb++) {
            m0 = fmaxf(m0, fmaxf(c[nb][0], c[nb][1]));
            m1 = fmaxf(m1, fmaxf(c[nb][2], c[nb][3]));
        }
        m0 = fmaxf(m0, __shfl_xor_sync(~0u, m0, 1));
        m0 = fmaxf(m0, __shfl_xor_sync(~0u, m0, 2));
        m1 = fmaxf(m1, __shfl_xor_sync(~0u, m1, 1));
        m1 = fmaxf(m1, __shfl_xor_sync(~0u, m1, 2));

        float s0 = 0.0f, s1 = 0.0f;
        unsigned p[25];
#pragma unroll
        for (int nb = 0; nb < 25; nb++) {
            float e0 = exp2f(c[nb][0] - m0);
            float e1 = exp2f(c[nb][1] - m0);
            float e2 = exp2f(c[nb][2] - m1);
            float e3 = exp2f(c[nb][3] - m1);
            s0 += e0 + e1;
            s1 += e2 + e3;
            __half2 lo = __floats2half2_rn(e0, e1);
            __half2 hi = __floats2half2_rn(e2, e3);
            p[nb] = h2_as_u(lo);
            c[nb][2] = __uint_as_float(h2_as_u(hi));
        }
        s0 += __shfl_xor_sync(~0u, s0, 1);
        s0 += __shfl_xor_sync(~0u, s0, 2);
        s1 += __shfl_xor_sync(~0u, s1, 1);
        s1 += __shfl_xor_sync(~0u, s1, 2);
        float rinv0 = 1.0f / s0, rinv1 = 1.0f / s1;

        float o[8][4];
#pragma unroll
        for (int d = 0; d < 8; d++)
#pragma unroll
            for (int j = 0; j < 4; j++) o[d][j] = 0.0f;

        const int lkv = ((lane >> 3) & 1) * 8 + (lane & 7);
        const int ldv = (lane >> 4) * 8;
#pragma unroll
        for (int kc = 0; kc < 13; kc++) {
            unsigned pa[4];
            pa[0] = p[2 * kc];
            pa[1] = __float_as_uint(c[2 * kc][2]);
            if (kc < 12) {
                pa[2] = p[2 * kc + 1];
                pa[3] = __float_as_uint(c[2 * kc + 1][2]);
            } else {
                pa[2] = 0; pa[3] = 0;
            }
#pragma unroll
            for (int dp = 0; dp < 4; dp++) {
                unsigned b0, b1, b2, b3;
                ldsm4t(b0, b1, b2, b3, Vsm + (kc * 16 + lkv) * 72 + dp * 16 + ldv);
                mma16816(o[2 * dp], pa, b0, b1);
                mma16816(o[2 * dp + 1], pa, b2, b3);
            }
        }

        if (row0 < NN) {
            __half2* op = reinterpret_cast<__half2*>(
                g_AO + (size_t)(b * NN + row0) * DIM + h * DH);
#pragma unroll
            for (int d = 0; d < 8; d++)
                op[d * 4 + ql] = __floats2half2_rn(o[d][0] * rinv0, o[d][1] * rinv0);
        }
        if (row1 < NN) {
            __half2* op = reinterpret_cast<__half2*>(
                g_AO + (size_t)(b * NN + row1) * DIM + h * DH);
#pragma unroll
            for (int d = 0; d < 8; d++)
                op[d * 4 + ql] = __floats2half2_rn(o[d][2] * rinv1, o[d][3] * rinv1);
        }
    }
}

// ---------------- launch ----------------
extern "C" void kernel_launch(void* const* d_in, const int* in_sizes, int n_in,
                              void* d_out, int out_size) {
    const float* x     = (const float*)d_in[0];
    const float* qkvw  = (const float*)d_in[1];
    const float* projw = (const float*)d_in[2];
    const float* projb = (const float*)d_in[3];
    const float* btab  = (const float*)d_in[4];
    const int*   ridx  = (const int*)d_in[5];
    float* out = (float*)d_out;

    cudaFuncSetAttribute(attn_kernel, cudaFuncAttributeMaxDynamicSharedMemorySize,
                         SMEM_ATTN);
    cudaFuncSetAttribute(gemm_kernel, cudaFuncAttributeMaxDynamicSharedMemorySize,
                         SMEM_G);

    prep_all<<<(NPREP + 255) / 256, 256>>>(x, qkvw, projw, btab, ridx);  // 0

    // QKV: M=25216 (197 tiles), N=2304 (18 tiles)                        // 1
    gemm_kernel<<<dim3(18, 197), 256, SMEM_G>>>(0, nullptr, nullptr);

    attn_kernel<<<BB * HH, ATHR, SMEM_ATTN>>>();                         // 2

    // proj: N=768 (6 tiles)                                              // 3 (profiled)
    gemm_kernel<<<dim3(6, 197), 256, SMEM_G>>>(1, projb, out);
}